// round 1
// baseline (speedup 1.0000x reference)
#include <cuda_runtime.h>
#include <math.h>

#define NNODES 5000
#define NEDGES 80000
#define CC     128
#define KA     10
#define SHD    16
#define NLL    4

// ---------------- scratch (static device globals; no allocation allowed) ----
__device__ float g_x  [NNODES * CC];          // linear_up output
__device__ float g_h1 [NEDGES * 64];          // MLP ping
__device__ float g_h2 [NEDGES * 64];          // MLP pong
__device__ float g_tpw[NEDGES * NLL * CC];    // per-edge TP weights [E,4,128]
__device__ float g_m  [NNODES * CC * SHD];    // scattered messages [N,128,16]
__device__ float g_t  [NNODES * CC * SHD];    // after per-l linear [N,128,16]

__device__ __forceinline__ float silu_f(float v) { return v / (1.0f + __expf(-v)); }

// ---------------------------------------------------------------------------
// Generic tiled SGEMM:  C[M,N] = epilogue( A[M,K] @ B[K,N] * scale )
// BM=128, BN=64, BK=8, 256 threads, per-thread 8x4 register tile.
// ---------------------------------------------------------------------------
template <bool DOSILU>
__global__ void sgemm_k(const float* __restrict__ A, const float* __restrict__ B,
                        float* __restrict__ Cm, int M, int N, int K, float scale)
{
    __shared__ float As[8][128];
    __shared__ float Bs[8][64];

    const int tid = threadIdx.x;          // 0..255
    const int tx  = tid & 15;             // col group (16 * 4 = 64 cols)
    const int ty  = tid >> 4;             // row group (16 * 8 = 128 rows)
    const int rowBase = blockIdx.x * 128;
    const int colBase = blockIdx.y * 64;

    float acc[8][4];
#pragma unroll
    for (int i = 0; i < 8; i++)
#pragma unroll
        for (int j = 0; j < 4; j++) acc[i][j] = 0.0f;

    const int lrow = tid >> 1;            // 0..127
    const int lk   = (tid & 1) * 4;       // 0 or 4
    const int brow = tid >> 5;            // 0..7
    const int bcol = (tid & 31) * 2;      // 0..62

    for (int kt = 0; kt < K; kt += 8) {
        float4 av = make_float4(0.f, 0.f, 0.f, 0.f);
        int gr = rowBase + lrow;
        if (gr < M)
            av = *reinterpret_cast<const float4*>(A + (size_t)gr * K + kt + lk);
        As[lk + 0][lrow] = av.x; As[lk + 1][lrow] = av.y;
        As[lk + 2][lrow] = av.z; As[lk + 3][lrow] = av.w;

        float2 bv = *reinterpret_cast<const float2*>(B + (size_t)(kt + brow) * N + colBase + bcol);
        Bs[brow][bcol] = bv.x; Bs[brow][bcol + 1] = bv.y;
        __syncthreads();

#pragma unroll
        for (int kk = 0; kk < 8; kk++) {
            float4 a0 = *reinterpret_cast<const float4*>(&As[kk][ty * 8]);
            float4 a1 = *reinterpret_cast<const float4*>(&As[kk][ty * 8 + 4]);
            float4 b  = *reinterpret_cast<const float4*>(&Bs[kk][tx * 4]);
            float am[8] = {a0.x, a0.y, a0.z, a0.w, a1.x, a1.y, a1.z, a1.w};
            float bm[4] = {b.x, b.y, b.z, b.w};
#pragma unroll
            for (int i = 0; i < 8; i++)
#pragma unroll
                for (int j = 0; j < 4; j++) acc[i][j] += am[i] * bm[j];
        }
        __syncthreads();
    }

#pragma unroll
    for (int i = 0; i < 8; i++) {
        int gr = rowBase + ty * 8 + i;
        if (gr < M) {
            float4 o;
            o.x = acc[i][0] * scale; o.y = acc[i][1] * scale;
            o.z = acc[i][2] * scale; o.w = acc[i][3] * scale;
            if (DOSILU) { o.x = silu_f(o.x); o.y = silu_f(o.y); o.z = silu_f(o.z); o.w = silu_f(o.w); }
            *reinterpret_cast<float4*>(Cm + (size_t)gr * N + colBase + tx * 4) = o;
        }
    }
}

// ---------------------------------------------------------------------------
__global__ void zero_k(float* __restrict__ p, int n)
{
    int i = blockIdx.x * blockDim.x + threadIdx.x;
    if (i < n) p[i] = 0.0f;
}

// ---------------------------------------------------------------------------
// Fused edge tensor product + scatter:
//   m[recv, c, i] += x[send, c] * tpw[e, l(i), c] * sh[e, i]
// One block (256 thr) per edge; consecutive tids hit consecutive addresses
// so the 8 atomicAdd rounds per thread are fully coalesced.
// ---------------------------------------------------------------------------
__global__ void scatter_k(const float* __restrict__ edge_attrs, const int* __restrict__ eidx)
{
    const int e   = blockIdx.x;
    const int tid = threadIdx.x;           // 0..255
    __shared__ float sx[CC];
    __shared__ float sw[NLL * CC];
    __shared__ float ssh[SHD];

    const int s = eidx[e];
    const int r = eidx[NEDGES + e];

    if (tid < CC) sx[tid] = g_x[s * CC + tid];
    sw[tid]       = g_tpw[(size_t)e * 512 + tid];
    sw[tid + 256] = g_tpw[(size_t)e * 512 + 256 + tid];
    if (tid < SHD) ssh[tid] = edge_attrs[(size_t)e * SHD + tid];
    __syncthreads();

    float* mrow = g_m + (size_t)r * (CC * SHD);
#pragma unroll
    for (int j = 0; j < 8; j++) {
        int idx = j * 256 + tid;           // 0..2047  ==  c*16 + i
        int c = idx >> 4;
        int i = idx & 15;
        int l = (i == 0) ? 0 : (i < 4) ? 1 : (i < 9) ? 2 : 3;
        atomicAdd(mrow + idx, sx[c] * sw[l * CC + c] * ssh[i]);
    }
}

// ---------------------------------------------------------------------------
// Per-l channel mixing: t[n,v,i] = (sum_u m[n,u,i] * W_lin[l,u,v]) /sqrt(C)/16
// 2 nodes per block, 128 threads (v). W_lin streamed from L2 (640MB total).
// ---------------------------------------------------------------------------
__global__ void lin_k(const float* __restrict__ W_lin)
{
    const int n0 = blockIdx.x * 2;
    const int v  = threadIdx.x;            // 0..127
    __shared__ float sm[2][CC * SHD];

    for (int nn = 0; nn < 2; nn++)
        for (int idx = v; idx < CC * SHD; idx += 128)
            sm[nn][idx] = g_m[(size_t)(n0 + nn) * CC * SHD + idx];
    __syncthreads();

    float acc[2][16];
#pragma unroll
    for (int nn = 0; nn < 2; nn++)
#pragma unroll
        for (int i = 0; i < 16; i++) acc[nn][i] = 0.0f;

    for (int u = 0; u < CC; u++) {
        float wl[4];
        wl[0] = W_lin[(0 * CC + u) * CC + v];
        wl[1] = W_lin[(1 * CC + u) * CC + v];
        wl[2] = W_lin[(2 * CC + u) * CC + v];
        wl[3] = W_lin[(3 * CC + u) * CC + v];
#pragma unroll
        for (int i = 0; i < 16; i++) {
            const int l = (i == 0) ? 0 : (i < 4) ? 1 : (i < 9) ? 2 : 3;  // folds at compile time
            float wv = wl[l];
#pragma unroll
            for (int nn = 0; nn < 2; nn++)
                acc[nn][i] += wv * sm[nn][u * 16 + i];
        }
    }

    const float sc = 0.005524271728019903f;   // 1/sqrt(128)/16
#pragma unroll
    for (int nn = 0; nn < 2; nn++) {
        float* dst = g_t + (size_t)(n0 + nn) * CC * SHD + v * 16;
#pragma unroll
        for (int q = 0; q < 4; q++) {
            float4 o;
            o.x = acc[nn][q * 4 + 0] * sc; o.y = acc[nn][q * 4 + 1] * sc;
            o.z = acc[nn][q * 4 + 2] * sc; o.w = acc[nn][q * 4 + 3] * sc;
            *reinterpret_cast<float4*>(dst + q * 4) = o;
        }
    }
}

// ---------------------------------------------------------------------------
// Skip tensor product, factored:
//   out[n,w,i] = (1/sqrt(C*K)) * sum_u t[n,u,i] * (sum_k attr[n,k] W_skip[l,u,k,w])
// Inner dim per u is (K + dim_l) instead of K*dim_l -> 4.6 GMAC total.
// TN=4 nodes per block, 128 threads (w). W_skip stays L2-resident (2.6MB).
// ---------------------------------------------------------------------------
template <int L, int DL, int OFFV>
__global__ void skip_k(const float* __restrict__ node_attrs,
                       const float* __restrict__ W_skip,
                       float* __restrict__ out)
{
    constexpr int TN = 4;
    const int n0 = blockIdx.x * TN;
    const int w  = threadIdx.x;            // 0..127
    __shared__ float st[TN][CC * DL];
    __shared__ float sattr[TN][KA];

    for (int nn = 0; nn < TN; nn++)
        for (int idx = w; idx < CC * DL; idx += 128) {
            int u = idx / DL, i = idx % DL;
            st[nn][idx] = g_t[(size_t)(n0 + nn) * CC * SHD + u * SHD + OFFV + i];
        }
    if (w < TN * KA) sattr[w / KA][w % KA] = node_attrs[(size_t)(n0 + w / KA) * KA + (w % KA)];
    __syncthreads();

    float acc[TN][DL];
#pragma unroll
    for (int nn = 0; nn < TN; nn++)
#pragma unroll
        for (int i = 0; i < DL; i++) acc[nn][i] = 0.0f;

    const float* Wb = W_skip + (size_t)(L * CC) * KA * CC + w;
    for (int u = 0; u < CC; u++) {
        float sW[TN] = {0.f, 0.f, 0.f, 0.f};
#pragma unroll
        for (int k = 0; k < KA; k++) {
            float wv = Wb[(size_t)(u * KA + k) * CC];
#pragma unroll
            for (int nn = 0; nn < TN; nn++) sW[nn] += sattr[nn][k] * wv;
        }
#pragma unroll
        for (int nn = 0; nn < TN; nn++)
#pragma unroll
            for (int i = 0; i < DL; i++) acc[nn][i] += sW[nn] * st[nn][u * DL + i];
    }

    const float sc = 0.027950849718747374f;   // 1/sqrt(1280)
#pragma unroll
    for (int nn = 0; nn < TN; nn++)
#pragma unroll
        for (int i = 0; i < DL; i++)
            out[(size_t)(n0 + nn) * CC * SHD + w * SHD + OFFV + i] = acc[nn][i] * sc;
}

// ---------------------------------------------------------------------------
extern "C" void kernel_launch(void* const* d_in, const int* in_sizes, int n_in,
                              void* d_out, int out_size)
{
    const float* node_attrs = (const float*)d_in[0];
    const float* node_feats = (const float*)d_in[1];
    const float* edge_attrs = (const float*)d_in[2];
    const float* edge_feats = (const float*)d_in[3];
    const int*   edge_index = (const int*)  d_in[4];
    const float* W_up  = (const float*)d_in[5];
    const float* rW0   = (const float*)d_in[6];
    const float* rW1   = (const float*)d_in[7];
    const float* rW2   = (const float*)d_in[8];
    const float* rW3   = (const float*)d_in[9];
    const float* W_lin = (const float*)d_in[10];
    const float* W_skip= (const float*)d_in[11];
    float* out = (float*)d_out;

    float *px, *ph1, *ph2, *ptpw, *pm;
    cudaGetSymbolAddress((void**)&px,   g_x);
    cudaGetSymbolAddress((void**)&ph1,  g_h1);
    cudaGetSymbolAddress((void**)&ph2,  g_h2);
    cudaGetSymbolAddress((void**)&ptpw, g_tpw);
    cudaGetSymbolAddress((void**)&pm,   g_m);

    // 1) linear_up: x = node_feats @ W_up / sqrt(128)
    sgemm_k<false><<<dim3(40, 2), 256>>>(node_feats, W_up, px, NNODES, CC, CC,
                                         0.08838834764831845f);

    // 2) radial MLP: 8 -> 64 -> 64 -> 64 -> 512
    sgemm_k<true ><<<dim3(625, 1), 256>>>(edge_feats, rW0, ph1, NEDGES, 64, 8,
                                          0.35355339059327373f);   // 1/sqrt(8)
    sgemm_k<true ><<<dim3(625, 1), 256>>>(ph1, rW1, ph2, NEDGES, 64, 64, 0.125f);
    sgemm_k<true ><<<dim3(625, 1), 256>>>(ph2, rW2, ph1, NEDGES, 64, 64, 0.125f);
    sgemm_k<false><<<dim3(625, 8), 256>>>(ph1, rW3, ptpw, NEDGES, 512, 64, 0.125f);

    // 3) zero message buffer, then fused edge TP + atomic scatter
    zero_k<<<(NNODES * CC * SHD + 255) / 256, 256>>>(pm, NNODES * CC * SHD);
    scatter_k<<<NEDGES, 256>>>(edge_attrs, edge_index);

    // 4) per-l channel mixing
    lin_k<<<NNODES / 2, 128>>>(W_lin);

    // 5) skip tensor product with node attrs -> output
    skip_k<0, 1, 0><<<NNODES / 4, 128>>>(node_attrs, W_skip, out);
    skip_k<1, 3, 1><<<NNODES / 4, 128>>>(node_attrs, W_skip, out);
    skip_k<2, 5, 4><<<NNODES / 4, 128>>>(node_attrs, W_skip, out);
    skip_k<3, 7, 9><<<NNODES / 4, 128>>>(node_attrs, W_skip, out);
}